// round 16
// baseline (speedup 1.0000x reference)
#include <cuda_runtime.h>
#include <cuda_fp16.h>
#include <math.h>
#include <stdint.h>

#define BB 4
#define SS 2048
#define DMODEL 1024
#define NH 16
#define DKV 64
#define INNER 1024
#define QSTR 3072              // fused QKV row stride
#define BS_TOT (BB * SS)
#define NREL 4095
#define LOG2E 1.4426950408889634f

// ---------------- scratch (device globals: allocation-free) ----------------
__device__ __align__(256) float g_biasTab[NH * NREL];
__device__ __align__(256) __half g_Hh[BS_TOT * DMODEL];
__device__ __align__(256) __half g_Hl[BS_TOT * DMODEL];
__device__ __align__(256) __half g_QKVh[BS_TOT * QSTR];
__device__ __align__(256) __half g_QKVl[BS_TOT * QSTR];
__device__ __align__(256) __half g_Ch[BS_TOT * INNER];
__device__ __align__(256) __half g_WTh[QSTR * DMODEL];   // [Wq*log2e;Wk;Wv]^T
__device__ __align__(256) __half g_WTl[QSTR * DMODEL];
__device__ __align__(256) __half g_WoTh[DMODEL * INNER];
__device__ __align__(256) __half g_WoTl[DMODEL * INNER];

// ---------------------------- PTX helpers ----------------------------------
__device__ __forceinline__ uint32_t smem_u32(const void* p) {
    uint32_t a;
    asm("{ .reg .u64 t; cvta.to.shared.u64 t, %1; cvt.u32.u64 %0, t; }"
        : "=r"(a) : "l"(p));
    return a;
}
__device__ __forceinline__ void cp16(uint32_t dst, const void* src) {
    asm volatile("cp.async.cg.shared.global [%0], [%1], 16;"
                 :: "r"(dst), "l"(src) : "memory");
}
__device__ __forceinline__ void cp4(uint32_t dst, const void* src) {
    asm volatile("cp.async.ca.shared.global [%0], [%1], 4;"
                 :: "r"(dst), "l"(src) : "memory");
}
__device__ __forceinline__ void cp_commit() {
    asm volatile("cp.async.commit_group;" ::: "memory");
}
__device__ __forceinline__ void cp_wait0() {
    asm volatile("cp.async.wait_group 0;" ::: "memory");
}
__device__ __forceinline__ void cp_wait1() {
    asm volatile("cp.async.wait_group 1;" ::: "memory");
}
__device__ __forceinline__ void cp_wait2() {
    asm volatile("cp.async.wait_group 2;" ::: "memory");
}
__device__ __forceinline__ void ldmx4(uint32_t* r, uint32_t addr) {
    asm volatile("ldmatrix.sync.aligned.m8n8.x4.shared.b16 {%0,%1,%2,%3}, [%4];"
                 : "=r"(r[0]), "=r"(r[1]), "=r"(r[2]), "=r"(r[3]) : "r"(addr));
}
__device__ __forceinline__ void ldmx4t(uint32_t* r, uint32_t addr) {
    asm volatile("ldmatrix.sync.aligned.m8n8.x4.trans.shared.b16 {%0,%1,%2,%3}, [%4];"
                 : "=r"(r[0]), "=r"(r[1]), "=r"(r[2]), "=r"(r[3]) : "r"(addr));
}
__device__ __forceinline__ void mma16816(float* c, const uint32_t* a,
                                         uint32_t b0, uint32_t b1) {
    asm volatile("mma.sync.aligned.m16n8k16.row.col.f32.f16.f16.f32 "
                 "{%0,%1,%2,%3}, {%4,%5,%6,%7}, {%8,%9}, {%0,%1,%2,%3};"
                 : "+f"(c[0]), "+f"(c[1]), "+f"(c[2]), "+f"(c[3])
                 : "r"(a[0]), "r"(a[1]), "r"(a[2]), "r"(a[3]), "r"(b0), "r"(b1));
}
__device__ __forceinline__ float ex2f(float x) {
    float y;
    asm("ex2.approx.ftz.f32 %0, %1;" : "=f"(y) : "f"(x));
    return y;
}
__device__ __forceinline__ uint32_t pack_hf2(float x, float y) {
    __half2 p = __floats2half2_rn(x, y);
    return *(uint32_t*)&p;
}
__device__ __forceinline__ void store_split2(__half* Ch, __half* Cl,
                                             size_t off, float x, float y) {
    __half hx = __float2half_rn(x), hy = __float2half_rn(y);
    __half lx = __float2half_rn(x - __half2float(hx));
    __half ly = __float2half_rn(y - __half2float(hy));
    *(__half2*)(Ch + off) = __halves2half2(hx, hy);
    *(__half2*)(Cl + off) = __halves2half2(lx, ly);
}

// ---------------------------------------------------------------------------
// fp32 -> fp16 hi/lo split (row-major)
// ---------------------------------------------------------------------------
__global__ __launch_bounds__(256) void split_plain(const float* __restrict__ X,
                                                   __half* __restrict__ Xh,
                                                   __half* __restrict__ Xl,
                                                   int n4) {
    int i = blockIdx.x * 256 + threadIdx.x;
    if (i >= n4) return;
    float4 v = ((const float4*)X)[i];
    __half h0 = __float2half_rn(v.x), h1 = __float2half_rn(v.y);
    __half h2 = __float2half_rn(v.z), h3 = __float2half_rn(v.w);
    __half l0 = __float2half_rn(v.x - __half2float(h0));
    __half l1 = __float2half_rn(v.y - __half2float(h1));
    __half l2 = __float2half_rn(v.z - __half2float(h2));
    __half l3 = __float2half_rn(v.w - __half2float(h3));
    ((__half2*)Xh)[2 * i]     = __halves2half2(h0, h1);
    ((__half2*)Xh)[2 * i + 1] = __halves2half2(h2, h3);
    ((__half2*)Xl)[2 * i]     = __halves2half2(l0, l1);
    ((__half2*)Xl)[2 * i + 1] = __halves2half2(l2, l3);
}

// ---------------------------------------------------------------------------
// Weight transpose + split, with T5 bias table fused in (z==3 blocks).
// Wq (z==0) and the bias table are pre-scaled by log2(e).
// ---------------------------------------------------------------------------
__device__ __forceinline__ void transp_tile(const float* __restrict__ W,
                                            __half* __restrict__ Th,
                                            __half* __restrict__ Tl,
                                            float scale) {
    __shared__ float t[32][33];
    int bx = blockIdx.x * 32, by = blockIdx.y * 32;
    int tx = threadIdx.x, ty = threadIdx.y;
#pragma unroll
    for (int i = 0; i < 32; i += 8)
        t[ty + i][tx] = W[(size_t)(by + ty + i) * DMODEL + bx + tx];
    __syncthreads();
#pragma unroll
    for (int i = 0; i < 32; i += 8) {
        float v = t[tx][ty + i] * scale;
        __half h = __float2half_rn(v);
        __half l = __float2half_rn(v - __half2float(h));
        size_t o = (size_t)(bx + ty + i) * DMODEL + by + tx;
        Th[o] = h;
        Tl[o] = l;
    }
}
__global__ __launch_bounds__(256)
void split_transpose3b(const float* __restrict__ Wq, const float* __restrict__ Wk,
                       const float* __restrict__ Wv, const float* __restrict__ rel_emb,
                       __half* __restrict__ Th, __half* __restrict__ Tl,
                       float* __restrict__ biasTab) {
    if (blockIdx.z < 3) {
        const float* W = (blockIdx.z == 0) ? Wq : (blockIdx.z == 1) ? Wk : Wv;
        float sc = (blockIdx.z == 0) ? LOG2E : 1.0f;
        size_t off = (size_t)blockIdx.z * DMODEL * DMODEL;
        transp_tile(W, Th + off, Tl + off, sc);
        return;
    }
    int tid = threadIdx.y * 32 + threadIdx.x;
    int idx = (blockIdx.y * 32 + blockIdx.x) * 256 + tid;
    if (idx >= NH * NREL) return;
    int h = idx / NREL;
    int pos = idx - h * NREL;
    int rel = pos - (SS - 1);
    int n = -rel;
    int ret = 0;
    if (n < 0) { ret = 16; n = -n; }
    int bucket;
    if (n < 8) {
        bucket = ret + n;
    } else {
        float v = logf((float)n / 8.0f) / logf(16.0f) * 8.0f;
        int vi = 8 + (int)v;
        if (vi > 15) vi = 15;
        bucket = ret + vi;
    }
    biasTab[h * NREL + pos] = rel_emb[bucket * NH + h] * LOG2E;
}
__global__ __launch_bounds__(256)
void split_transpose1(const float* __restrict__ W,
                      __half* __restrict__ Th, __half* __restrict__ Tl) {
    transp_tile(W, Th, Tl, 1.0f);
}

// ---------------------------------------------------------------------------
// Split-fp16 mma.sync GEMM: C[M,N] = A[M,K] @ BT[N,K]^T
// CTA tile 128(M) x 64(N), BK=16, 256 threads = 8 warps (4x2), warp 32x32.
// FOUR-stage cp.async ring (wait_group 2): each load gets 3 chunk-windows.
// Row stride 48B (conflict-free for ldsm). 3 CTAs/SM (221KB smem total).
// Column-blocks < p3_end: 3 products; >= p3_end: 1 product (A-hi x B-hi).
// ---------------------------------------------------------------------------
#define LDSB 48
#define SG_A_L 6144
#define SG_B_H 12288
#define SG_B_L 15360
#define SG_SZ  18432

__global__ __launch_bounds__(256, 3)
void mma_gemm(const __half* __restrict__ Ah, const __half* __restrict__ Al,
              const __half* __restrict__ Bh, const __half* __restrict__ Bl,
              float* __restrict__ Cf,
              __half* __restrict__ Ch, __half* __restrict__ Cl,
              int M, int N, int K, int split_out, int p3_end) {
    extern __shared__ __align__(128) char smem[];
    const int tid = threadIdx.x, lane = tid & 31, wid = tid >> 5;
    const int wm = wid >> 1, wn = wid & 1;           // 4 x 2 warp grid
    const int rowA0 = blockIdx.y * 128, rowB0 = blockIdx.x * 64;
    const uint32_t sb = smem_u32(smem);
    const int nk = K >> 4;                           // BK = 16
    const bool np3 = ((int)blockIdx.x < p3_end);

    float acc[8][4];
#pragma unroll
    for (int i = 0; i < 8; i++)
#pragma unroll
        for (int j = 0; j < 4; j++) acc[i][j] = 0.0f;

    // ---- per-thread load geometry: A row=tid>>1, 16B chunk=(tid&1)*16 ----
    const int ar = tid >> 1, ac = (tid & 1) << 4;
    const char* pAh = (const char*)Ah + ((size_t)(rowA0 + ar) * K) * 2 + ac;
    const char* pAl = (const char*)Al + ((size_t)(rowA0 + ar) * K) * 2 + ac;
    const uint32_t dA = (uint32_t)ar * LDSB + ac;
    const int bt2 = tid & 127;
    const int br = bt2 >> 1, bc = (bt2 & 1) << 4;
    const bool isBh = tid < 128;
    const char* pB = (const char*)(isBh ? Bh : Bl)
                   + ((size_t)(rowB0 + br) * K) * 2 + bc;
    const uint32_t dBo = (isBh ? SG_B_H : SG_B_L) + (uint32_t)br * LDSB + bc;
    const bool doB = isBh || np3;

    auto load_stage = [&](int stage) {
        const uint32_t d0 = sb + (uint32_t)stage * SG_SZ;
        cp16(d0 + dA, pAh);
        if (np3) cp16(d0 + SG_A_L + dA, pAl);
        if (doB) cp16(d0 + dBo, pB);
        pAh += 32; pAl += 32; pB += 32;              // advance one BK=16 chunk
        cp_commit();
    };

    load_stage(0);
    load_stage(1);
    load_stage(2);

    const int rA = lane & 15;
    const int cA8b = ((lane >> 4) << 3) * 2;         // byte col offset 0/16

    for (int kc = 0; kc < nk; kc++) {
        if (kc <= nk - 3)      cp_wait2();
        else if (kc == nk - 2) cp_wait1();
        else                   cp_wait0();
        __syncthreads();
        if (kc + 3 < nk) load_stage((kc + 3) & 3);

        const uint32_t base = sb + (uint32_t)(kc & 3) * SG_SZ;
        uint32_t a_h[2][4], a_l[2][4], b_h[2][4], b_l[2][4];
#pragma unroll
        for (int jb = 0; jb < 2; jb++) {
            uint32_t boff = (uint32_t)(32 * wn + jb * 16 + rA) * LDSB + cA8b;
            ldmx4(b_h[jb], base + SG_B_H + boff);
            if (np3) ldmx4(b_l[jb], base + SG_B_L + boff);
        }
#pragma unroll
        for (int im = 0; im < 2; im++) {
            uint32_t aoff = (uint32_t)(32 * wm + im * 16 + rA) * LDSB + cA8b;
            ldmx4(a_h[im], base + aoff);
            if (np3) ldmx4(a_l[im], base + SG_A_L + aoff);
        }
        // product 1: Ah x Bh (8 independent accumulators)
#pragma unroll
        for (int im = 0; im < 2; im++)
#pragma unroll
            for (int jn = 0; jn < 4; jn++) {
                int jb = jn >> 1, sub = jn & 1;
                mma16816(acc[im * 4 + jn], a_h[im], b_h[jb][sub], b_h[jb][sub + 2]);
            }
        if (np3) {
            // product 2: Ah x Bl
#pragma unroll
            for (int im = 0; im < 2; im++)
#pragma unroll
                for (int jn = 0; jn < 4; jn++) {
                    int jb = jn >> 1, sub = jn & 1;
                    mma16816(acc[im * 4 + jn], a_h[im], b_l[jb][sub], b_l[jb][sub + 2]);
                }
            // product 3: Al x Bh
#pragma unroll
            for (int im = 0; im < 2; im++)
#pragma unroll
                for (int jn = 0; jn < 4; jn++) {
                    int jb = jn >> 1, sub = jn & 1;
                    mma16816(acc[im * 4 + jn], a_l[im], b_h[jb][sub], b_h[jb][sub + 2]);
                }
        }
    }

    const int er = lane >> 2, ec = (lane & 3) << 1;
#pragma unroll
    for (int im = 0; im < 2; im++) {
        int r0 = rowA0 + 32 * wm + im * 16 + er;
#pragma unroll
        for (int jn = 0; jn < 4; jn++) {
            int c = rowB0 + 32 * wn + jn * 8 + ec;
            float* a = acc[im * 4 + jn];
            if (split_out) {
                if (np3) {
                    store_split2(Ch, Cl, (size_t)r0 * N + c, a[0], a[1]);
                    store_split2(Ch, Cl, (size_t)(r0 + 8) * N + c, a[2], a[3]);
                } else {
                    *(__half2*)(Ch + (size_t)r0 * N + c) =
                        __floats2half2_rn(a[0], a[1]);
                    *(__half2*)(Ch + (size_t)(r0 + 8) * N + c) =
                        __floats2half2_rn(a[2], a[3]);
                }
            } else {
                *(float2*)(Cf + (size_t)r0 * N + c) = make_float2(a[0], a[1]);
                *(float2*)(Cf + (size_t)(r0 + 8) * N + c) = make_float2(a[2], a[3]);
            }
        }
    }
}

// ---------------------------------------------------------------------------
// Register-resident FA2 flash attention (unchanged from round 15).
// ---------------------------------------------------------------------------
#define LKV 72
#define KBUF 18432
#define VBUF 9216
#define AQH 0
#define AQL 18432
#define AKB 36864
#define AVB 73728
#define ABI 92160
#define ATTN_SMEM 93696
#define NKT (SS / 64)

__global__ __launch_bounds__(256, 2)
void attn_fa2(const __half* __restrict__ Xh, const __half* __restrict__ Xl,
              const float* __restrict__ biasTab,
              __half* __restrict__ Ch) {
    extern __shared__ __align__(128) char sm[];
    const int tid = threadIdx.x, lane = tid & 31, wid = tid >> 5;
    const int qt = blockIdx.x, bhi = blockIdx.y;
    const int b = bhi >> 4, h = bhi & 15;
    const int q0 = qt * 128;
    const size_t ibase = (size_t)b * SS * QSTR + (size_t)h * DKV;
    const size_t obase = (size_t)b * SS * INNER + (size_t)h * DKV;
    const uint32_t sb = smem_u32(sm);

    const int rA = lane & 15, cA8 = (lane >> 4) << 3;
    const int er = lane >> 2, qr = (lane & 3) << 1;
    const int r0 = wid * 16 + er, r1 = r0 + 8;

    const int lrow = tid >> 3;
    const int lch  = (tid & 7) << 4;
    const uint32_t goffA = (uint32_t)lrow * (QSTR * 2) + lch;
    const uint32_t goffB = goffA + 32 * QSTR * 2;
    const uint32_t sA = (uint32_t)lrow * 144 + lch;
    const uint32_t sB = sA + 32 * 144;
    const char* srcKh = (const char*)Xh + (ibase + 1024) * 2;
    const char* srcKl = (const char*)Xl + (ibase + 1024) * 2;
    const char* srcV  = (const char*)Xh + (ibase + 2048) * 2;
    const float* srcB = biasTab + h * NREL + (SS - 1) - q0 - 127;

    auto loadKV = [&](int buf) {
        uint32_t kd = sb + AKB + (uint32_t)buf * KBUF;
        uint32_t vd = sb + AVB + (uint32_t)buf * VBUF;
        cp16(kd + sA, srcKh + goffA);
        cp16(kd + sB, srcKh + goffB);
        cp16(kd + 9216 + sA, srcKl + goffA);
        cp16(kd + 9216 + sB, srcKl + goffB);
        cp16(vd + sA, srcV + goffA);
        cp16(vd + sB, srcV + goffB);
        if (tid < 191)
            cp4(sb + ABI + (uint32_t)buf * 768 + tid * 4, srcB + tid);
        srcKh += (size_t)64 * QSTR * 2;
        srcKl += (size_t)64 * QSTR * 2;
        srcV  += (size_t)64 * QSTR * 2;
        srcB  += 64;
        cp_commit();
    };

#pragma unroll
    for (int i = 0; i < 8; i++) {
        int id = tid + i * 256;
        int arr = id >> 10, rem = id & 1023;
        int row = rem >> 3, ch = (rem & 7) << 4;
        const __half* src = arr ? Xl : Xh;
        cp16(sb + (arr ? AQL : AQH) + row * 144 + ch,
             (const char*)src + (ibase + (size_t)(q0 + row) * QSTR) * 2 + ch);
    }
    loadKV(0);

    float m0 = -1e30f, m1 = -1e30f, l0 = 0.0f, l1 = 0.0f;
    float oac[8][4];
#pragma unroll
    for (int i = 0; i < 8; i++)
#pragma unroll
        for (int j = 0; j < 4; j++) oac[i][j] = 0.0f;

    for (int kt = 0; kt < NKT; kt++) {
        const int buf = kt & 1;
        cp_wait0();
        __syncthreads();                       // ONE barrier per tile
        if (kt + 1 < NKT) loadKV(buf ^ 1);

        const uint32_t kb0 = sb + AKB + (uint32_t)buf * KBUF;
        const uint32_t kb1 = kb0 + 9216;
        const uint32_t vb  = sb + AVB + (uint32_t)buf * VBUF;
        const float* bias_s = (const float*)(sm + ABI + buf * 768);

        float sac[8][4];
#pragma unroll
        for (int i = 0; i < 8; i++)
#pragma unroll
            for (int j = 0; j < 4; j++) sac[i][j] = 0.0f;
#pragma unroll
        for (int ks = 0; ks < 64; ks += 16) {
            uint32_t qfh[4], qfl[4], khf[4][4], klf[4][4];
            uint32_t aoff = ((wid * 16 + rA) * LKV + ks + cA8) * 2;
            ldmx4(qfh, sb + AQH + aoff);
            ldmx4(qfl, sb + AQL + aoff);
#pragma unroll
            for (int kb = 0; kb < 4; kb++) {
                uint32_t boff = ((16 * kb + rA) * LKV + ks + cA8) * 2;
                ldmx4(khf[kb], kb0 + boff);
                ldmx4(klf[kb], kb1 + boff);
            }
#pragma unroll
            for (int jn = 0; jn < 8; jn++) {
                int kb = jn >> 1, sub = jn & 1;
                mma16816(sac[jn], qfh, khf[kb][sub], khf[kb][sub + 2]);
            }
#pragma unroll
            for (int jn = 0; jn < 8; jn++) {
                int kb = jn >> 1, sub = jn & 1;
                mma16816(sac[jn], qfh, klf[kb][sub], klf[kb][sub + 2]);
            }
#pragma unroll
            for (int jn = 0; jn < 8; jn++) {
                int kb = jn >> 1, sub = jn & 1;
                mma16816(sac[jn], qfl, khf[kb][sub], khf[kb][sub + 2]);
            }
        }

        float vx0 = -1e30f, vx1 = -1e30f;
#pragma unroll
        for (int jn = 0; jn < 8; jn++) {
            int c = jn * 8 + qr;
            sac[jn][0] += bias_s[c - r0 + 127];
            sac[jn][1] += bias_s[c + 1 - r0 + 127];
            sac[jn][2] += bias_s[c - r1 + 127];
            sac[jn][3] += bias_s[c + 1 - r1 + 127];
            vx0 = fmaxf(vx0, fmaxf(sac[jn][0], sac[jn][1]));
            vx1 = fmaxf(vx1, fmaxf(sac[jn][2], sac[jn][3]));
        }
#pragma unroll
        for (int off = 1; off < 4; off <<= 1) {
            vx0 = fmaxf(vx0, __shfl_xor_sync(0xffffffffu, vx0, off));
            vx1 = fmaxf(vx1, __shfl_xor_sync(0xffffffffu, vx1, off));
        }
        float mn0 = fmaxf(m0, vx0), mn1 = fmaxf(m1, vx1);
        float al0 = ex2f(m0 - mn0), al1 = ex2f(m1 - mn1);
        m0 = mn0; m1 = mn1;
        l0 *= al0; l1 *= al1;
#pragma unroll
        for (int jn = 0; jn < 8; jn++) {
            oac[jn][0] *= al0; oac[jn][1] *= al0;
            oac[jn][2] *= al1; oac[jn][3] *= al1;
        }

#pragma unroll
        for (int t = 0; t < 4; t++) {
            uint32_t vhf[4][4];
#pragma unroll
            for (int db = 0; db < 4; db++) {
                uint32_t voff = ((16 * t + rA) * LKV + 16 * db + cA8) * 2;
                ldmx4t(vhf[db], vb + voff);
            }
            uint32_t pfh[4];
#pragma unroll
            for (int half = 0; half < 2; half++) {
                int j = 2 * t + half;
                float e0 = ex2f(sac[j][0] - mn0);
                float e1 = ex2f(sac[j][1] - mn0);
                float e2 = ex2f(sac[j][2] - mn1);
                float e3 = ex2f(sac[j][3] - mn1);
                l0 += e0 + e1;
                l1 += e2 + e3;
                pfh[half * 2 + 0] = pack_hf2(e0, e1);
                pfh[half * 2 + 1] = pack_hf2(e2, e3);
            }
#pragma unroll
            for (int db = 0; db < 4; db++) {
                mma16816(oac[2 * db],     pfh, vhf[db][0], vhf[db][1]);
                mma16816(oac[2 * db + 1], pfh, vhf[db][2], vhf[db][3]);
            }
        }
    }

#pragma unroll
    for (int off = 1; off < 4; off <<= 1) {
        l0 += __shfl_xor_sync(0xffffffffu, l0, off);
        l1 += __shfl_xor_sync(0xffffffffu, l1, off);
    }

    float inv0 = 1.0f / l0, inv1 = 1.0f / l1;
#pragma unroll
    for (int jn = 0; jn < 8; jn++) {
        int c = jn * 8 + qr;
        *(__half2*)(Ch + obase + (size_t)(q0 + r0) * INNER + c) =
            __floats2half2_rn(oac[jn][0] * inv0, oac[jn][1] * inv0);
        *(__half2*)(Ch + obase + (size_t)(q0 + r1) * INNER + c) =
            __floats2half2_rn(oac[jn][2] * inv1, oac[jn][3] * inv1);
    }
}

// ---------------------------------------------------------------------------
extern "C" void kernel_launch(void* const* d_in, const int* in_sizes, int n_in,
                              void* d_out, int out_size) {
    const float* hidden = (const float*)d_in[0];
    const float* Wq     = (const float*)d_in[1];
    const float* Wk     = (const float*)d_in[2];
    const float* Wv     = (const float*)d_in[3];
    const float* Wo     = (const float*)d_in[4];
    const float* rel    = (const float*)d_in[5];
    float* out = (float*)d_out;

    float* pB;
    __half *pHh, *pHl, *pXh, *pXl, *pCh;
    __half *pWTh, *pWTl, *pWoTh, *pWoTl;
    cudaGetSymbolAddress((void**)&pB, g_biasTab);
    cudaGetSymbolAddress((void**)&pHh, g_Hh);
    cudaGetSymbolAddress((void**)&pHl, g_Hl);
    cudaGetSymbolAddress((void**)&pXh, g_QKVh);
    cudaGetSymbolAddress((void**)&pXl, g_QKVl);
    cudaGetSymbolAddress((void**)&pCh, g_Ch);
    cudaGetSymbolAddress((void**)&pWTh, g_WTh);
    cudaGetSymbolAddress((void**)&pWTl, g_WTl);
    cudaGetSymbolAddress((void**)&pWoTh, g_WoTh);
    cudaGetSymbolAddress((void**)&pWoTl, g_WoTl);

    cudaFuncSetAttribute(mma_gemm,
                         cudaFuncAttributeMaxDynamicSharedMemorySize, 4 * SG_SZ);
    cudaFuncSetAttribute(attn_fa2,
                         cudaFuncAttributeMaxDynamicSharedMemorySize, ATTN_SMEM);

    // launch 1: split hidden to fp16 hi/lo
    int n4h = BS_TOT * DMODEL / 4;
    split_plain<<<n4h / 256, 256>>>(hidden, pHh, pHl, n4h);
    // launch 2: transpose+split Wq(*log2e)/Wk/Wv + bias table (*log2e)
    dim3 tblk(32, 8);
    split_transpose3b<<<dim3(32, 32, 4), tblk>>>(Wq, Wk, Wv, rel, pWTh, pWTl, pB);
    // launch 3: transpose+split Wo
    split_transpose1<<<dim3(32, 32), tblk>>>(Wo, pWoTh, pWoTl);
    // launch 4 (ncu capture slot): fused QKV projection
    //   Q,K col-blocks (<32): 3 products; V col-blocks (>=32): 1 product
    mma_gemm<<<dim3(QSTR / 64, BS_TOT / 128), 256, 4 * SG_SZ>>>(
        pHh, pHl, pWTh, pWTl, nullptr, pXh, pXl, BS_TOT, QSTR, DMODEL, 1, 32);
    // launch 5: attention -> single-fp16 context
    attn_fa2<<<dim3(SS / 128, BB * NH), 256, ATTN_SMEM>>>(
        pXh, pXl, pB, pCh);
    // launch 6: output projection, 1 product (Ch x Wo-hi) -> f32 out
    mma_gemm<<<dim3(DMODEL / 64, BS_TOT / 128), 256, 4 * SG_SZ>>>(
        pCh, pCh, pWoTh, pWoTh, out, nullptr, nullptr, BS_TOT, DMODEL, INNER, 0, 0);
}